// round 1
// baseline (speedup 1.0000x reference)
#include <cuda_runtime.h>

#define N 4096
#define D 1024
#define EPSV 1e-8f
#define MARGIN 0.1f

#define BM 128
#define BN 128
#define BK 16
#define PAD 4   // smem second-dim padding (132 words) keeps 16B alignment, kills read conflicts

__device__ float  g_nw[N];
__device__ float  g_no[N];
__device__ float  g_d[N];
__device__ double g_acc = 0.0;

__device__ __forceinline__ float warp_sum(float v) {
    #pragma unroll
    for (int off = 16; off > 0; off >>= 1)
        v += __shfl_down_sync(0xFFFFFFFFu, v, off);
    return v;
}

// Kernel 1: per-row ||W||, ||O||, and diagonal cosine d[i] = (W[i]·O[i]) / max(||W||·||O||, eps)
// one block (256 threads) per row; D/4 = 256 float4 elements -> exactly 1 per thread
__global__ void row_stats_kernel(const float* __restrict__ W, const float* __restrict__ O) {
    int row = blockIdx.x;
    int t = threadIdx.x;
    const float4 a = reinterpret_cast<const float4*>(W + (size_t)row * D)[t];
    const float4 b = reinterpret_cast<const float4*>(O + (size_t)row * D)[t];
    float ww = a.x*a.x + a.y*a.y + a.z*a.z + a.w*a.w;
    float oo = b.x*b.x + b.y*b.y + b.z*b.z + b.w*b.w;
    float wo = a.x*b.x + a.y*b.y + a.z*b.z + a.w*b.w;

    ww = warp_sum(ww); oo = warp_sum(oo); wo = warp_sum(wo);

    __shared__ float sw[8], so[8], sd[8];
    int lane = t & 31, wid = t >> 5;
    if (lane == 0) { sw[wid] = ww; so[wid] = oo; sd[wid] = wo; }
    __syncthreads();
    if (wid == 0) {
        float vw = (lane < 8) ? sw[lane] : 0.f;
        float vo = (lane < 8) ? so[lane] : 0.f;
        float vd = (lane < 8) ? sd[lane] : 0.f;
        vw = warp_sum(vw); vo = warp_sum(vo); vd = warp_sum(vd);
        if (lane == 0) {
            float nw = sqrtf(vw);
            float no = sqrtf(vo);
            g_nw[row] = nw;
            g_no[row] = no;
            g_d[row]  = vd / fmaxf(nw * no, EPSV);
        }
    }
}

// Kernel 2: NT GEMM (both operands row-major [N, D], contraction over D) with fused
// cosine normalization + margin-loss epilogue, reduced into g_acc.
__global__ __launch_bounds__(256, 2)
void gemm_loss_kernel(const float* __restrict__ W, const float* __restrict__ O) {
    __shared__ float As[BK][BM + PAD];
    __shared__ float Bs[BK][BN + PAD];

    const int bi = blockIdx.y;
    const int bj = blockIdx.x;
    const int tid = threadIdx.x;
    const int tx = tid & 15;        // 0..15 -> 8 columns each
    const int ty = tid >> 4;        // 0..15 -> 8 rows each

    const int lrow = tid >> 2;      // 0..63 (two rows per thread: lrow, lrow+64)
    const int lc4  = tid & 3;       // which float4 of the 16-float k-slice

    const float* Abase = W + (size_t)(bi * BM) * D;
    const float* Bbase = O + (size_t)(bj * BN) * D;

    float acc[8][8];
    #pragma unroll
    for (int r = 0; r < 8; ++r)
        #pragma unroll
        for (int c = 0; c < 8; ++c)
            acc[r][c] = 0.f;

    for (int kt = 0; kt < D; kt += BK) {
        #pragma unroll
        for (int s = 0; s < 2; ++s) {
            int r = lrow + s * 64;
            float4 va = *reinterpret_cast<const float4*>(Abase + (size_t)r * D + kt + lc4 * 4);
            float4 vb = *reinterpret_cast<const float4*>(Bbase + (size_t)r * D + kt + lc4 * 4);
            As[lc4 * 4 + 0][r] = va.x;
            As[lc4 * 4 + 1][r] = va.y;
            As[lc4 * 4 + 2][r] = va.z;
            As[lc4 * 4 + 3][r] = va.w;
            Bs[lc4 * 4 + 0][r] = vb.x;
            Bs[lc4 * 4 + 1][r] = vb.y;
            Bs[lc4 * 4 + 2][r] = vb.z;
            Bs[lc4 * 4 + 3][r] = vb.w;
        }
        __syncthreads();

        #pragma unroll
        for (int k = 0; k < BK; ++k) {
            float a[8], b[8];
            #pragma unroll
            for (int r = 0; r < 8; ++r) a[r] = As[k][ty * 8 + r];
            #pragma unroll
            for (int c = 0; c < 8; ++c) b[c] = Bs[k][tx * 8 + c];
            #pragma unroll
            for (int r = 0; r < 8; ++r)
                #pragma unroll
                for (int c = 0; c < 8; ++c)
                    acc[r][c] = fmaf(a[r], b[c], acc[r][c]);
        }
        __syncthreads();
    }

    // ---- fused epilogue: cosine normalize + margin loss + reduce ----
    const int i0 = bi * BM + ty * 8;
    const int j0 = bj * BN + tx * 8;

    float nwv[8], dv[8], nov[8];
    #pragma unroll
    for (int r = 0; r < 8; ++r) { nwv[r] = g_nw[i0 + r]; dv[r] = g_d[i0 + r]; }
    #pragma unroll
    for (int c = 0; c < 8; ++c) { nov[c] = g_no[j0 + c]; }

    float lsum = 0.f;
    #pragma unroll
    for (int r = 0; r < 8; ++r) {
        #pragma unroll
        for (int c = 0; c < 8; ++c) {
            float S = acc[r][c] * __fdividef(1.0f, fmaxf(nwv[r] * nov[c], EPSV));
            float v;
            if (i0 + r == j0 + c) v = 1.0f - S;
            else                  v = fmaxf(MARGIN - S + dv[r], 0.0f);
            lsum += v;
        }
    }

    lsum = warp_sum(lsum);
    __shared__ float red[8];
    int lane = tid & 31, wid = tid >> 5;
    if (lane == 0) red[wid] = lsum;
    __syncthreads();
    if (wid == 0) {
        float v = (lane < 8) ? red[lane] : 0.f;
        v = warp_sum(v);
        if (lane == 0) atomicAdd(&g_acc, (double)v);
    }
}

// Kernel 3: finalize -> mean, and reset accumulator for next (graph-replayed) call
__global__ void finalize_kernel(float* __restrict__ out) {
    if (threadIdx.x == 0 && blockIdx.x == 0) {
        out[0] = (float)(g_acc / ((double)N * (double)N));
        g_acc = 0.0;
    }
}

extern "C" void kernel_launch(void* const* d_in, const int* in_sizes, int n_in,
                              void* d_out, int out_size) {
    const float* W = (const float*)d_in[0];   // wsi_embeddings  [N,1,D] fp32
    const float* O = (const float*)d_in[1];   // omic_embeddings [N,1,D] fp32
    float* out = (float*)d_out;

    row_stats_kernel<<<N, 256>>>(W, O);

    dim3 grid(N / BN, N / BM);
    gemm_loss_kernel<<<grid, 256>>>(W, O);

    finalize_kernel<<<1, 32>>>(out);
}

// round 3
// speedup vs baseline: 8.1695x; 8.1695x over previous
#include <cuda_runtime.h>
#include <cuda_bf16.h>
#include <cstdint>

#define N 4096
#define D 1024
#define EPSV 1e-8f
#define MARGIN 0.1f

#define BM 128
#define BN 128
#define BK 64          // 64 bf16 = 128 B per smem row (SW128 atom)
#define NKC (D / BK)   // 16 k-chunks

// ---------------- device globals (scratch) -----------------------------------
__device__ float  g_nw[N];
__device__ float  g_no[N];
__device__ float  g_d[N];
__device__ double g_acc = 0.0;
__device__ __nv_bfloat16 g_Wb[(size_t)N * D];
__device__ __nv_bfloat16 g_Ob[(size_t)N * D];

// ---------------- helpers ----------------------------------------------------
__device__ __forceinline__ uint32_t smem_u32(const void* p) {
    uint32_t a;
    asm("{ .reg .u64 t; cvta.to.shared.u64 t, %1; cvt.u32.u64 %0, t; }" : "=r"(a) : "l"(p));
    return a;
}
__device__ __forceinline__ float warp_sum(float v) {
    #pragma unroll
    for (int off = 16; off > 0; off >>= 1) v += __shfl_down_sync(0xFFFFFFFFu, v, off);
    return v;
}
__device__ __forceinline__ uint32_t swz128(uint32_t off) { return off ^ ((off >> 3) & 0x70); }

__device__ __forceinline__ void cp_async16(uint32_t saddr, const void* gaddr) {
    asm volatile("cp.async.cg.shared.global [%0], [%1], 16;" :: "r"(saddr), "l"(gaddr));
}
#define CP_COMMIT() asm volatile("cp.async.commit_group;" ::: "memory")
#define CP_WAIT0()  asm volatile("cp.async.wait_group 0;" ::: "memory")

__device__ __forceinline__ void ldsm_x4(uint32_t* r, uint32_t addr) {
    asm volatile("ldmatrix.sync.aligned.m8n8.x4.shared.b16 {%0,%1,%2,%3}, [%4];"
                 : "=r"(r[0]), "=r"(r[1]), "=r"(r[2]), "=r"(r[3]) : "r"(addr));
}
__device__ __forceinline__ void mma_bf16(float* c, const uint32_t* a, const uint32_t* b) {
    asm volatile(
        "mma.sync.aligned.m16n8k16.row.col.f32.bf16.bf16.f32 "
        "{%0,%1,%2,%3}, {%4,%5,%6,%7}, {%8,%9}, {%0,%1,%2,%3};"
        : "+f"(c[0]), "+f"(c[1]), "+f"(c[2]), "+f"(c[3])
        : "r"(a[0]), "r"(a[1]), "r"(a[2]), "r"(a[3]), "r"(b[0]), "r"(b[1]));
}

// ---------------- kernel 1: row stats + fp32->bf16 conversion ---------------
__global__ void row_stats_kernel(const float* __restrict__ W, const float* __restrict__ O) {
    int row = blockIdx.x;
    int t = threadIdx.x;
    const float4 a = reinterpret_cast<const float4*>(W + (size_t)row * D)[t];
    const float4 b = reinterpret_cast<const float4*>(O + (size_t)row * D)[t];

    __nv_bfloat162 a01 = __floats2bfloat162_rn(a.x, a.y);
    __nv_bfloat162 a23 = __floats2bfloat162_rn(a.z, a.w);
    __nv_bfloat162 b01 = __floats2bfloat162_rn(b.x, b.y);
    __nv_bfloat162 b23 = __floats2bfloat162_rn(b.z, b.w);
    uint2 pa = make_uint2(*(uint32_t*)&a01, *(uint32_t*)&a23);
    uint2 pb = make_uint2(*(uint32_t*)&b01, *(uint32_t*)&b23);
    reinterpret_cast<uint2*>(g_Wb + (size_t)row * D)[t] = pa;
    reinterpret_cast<uint2*>(g_Ob + (size_t)row * D)[t] = pb;

    float ww = a.x*a.x + a.y*a.y + a.z*a.z + a.w*a.w;
    float oo = b.x*b.x + b.y*b.y + b.z*b.z + b.w*b.w;
    float wo = a.x*b.x + a.y*b.y + a.z*b.z + a.w*b.w;

    ww = warp_sum(ww); oo = warp_sum(oo); wo = warp_sum(wo);

    __shared__ float sw[8], so[8], sd[8];
    int lane = t & 31, wid = t >> 5;
    if (lane == 0) { sw[wid] = ww; so[wid] = oo; sd[wid] = wo; }
    __syncthreads();
    if (wid == 0) {
        float vw = (lane < 8) ? sw[lane] : 0.f;
        float vo = (lane < 8) ? so[lane] : 0.f;
        float vd = (lane < 8) ? sd[lane] : 0.f;
        vw = warp_sum(vw); vo = warp_sum(vo); vd = warp_sum(vd);
        if (lane == 0) {
            float nw = sqrtf(vw), no = sqrtf(vo);
            g_nw[row] = nw; g_no[row] = no;
            g_d[row]  = vd / fmaxf(nw * no, EPSV);
        }
    }
}

// ---------------- kernel 2: mma.sync bf16 GEMM + fused loss ------------------
// dynamic smem: A0|A1|B0|B1 (16 KB each) then nw[128], d[128], no[128]
#define SM_A0    0
#define SM_A1    (SM_A0 + BM * 128)
#define SM_B0    (SM_A1 + BM * 128)
#define SM_B1    (SM_B0 + BN * 128)
#define SM_NW    (SM_B1 + BN * 128)
#define SM_D     (SM_NW + BM * 4)
#define SM_NO    (SM_D  + BM * 4)
#define SM_TOTAL (SM_NO + BN * 4)

__global__ __launch_bounds__(256, 2)
void gemm_loss_mma(void) {
    extern __shared__ char smem[];
    const uint32_t sbase = smem_u32(smem);
    const int tid  = threadIdx.x;
    const int wid  = tid >> 5;
    const int lane = tid & 31;
    const int bi = blockIdx.y;
    const int bj = blockIdx.x;
    const int warp_m = wid >> 2;       // 0..1  (64 rows each)
    const int warp_n = wid & 3;        // 0..3  (32 cols each)

    // stage per-row/col stats (visible after first __syncthreads)
    if (tid < 128) {
        reinterpret_cast<float*>(smem + SM_NW)[tid] = g_nw[bi * BM + tid];
        reinterpret_cast<float*>(smem + SM_D )[tid] = g_d [bi * BM + tid];
        reinterpret_cast<float*>(smem + SM_NO)[tid] = g_no[bj * BN + tid];
    }

    const __nv_bfloat16* __restrict__ Wt = g_Wb + (size_t)(bi * BM) * D;
    const __nv_bfloat16* __restrict__ Ot = g_Ob + (size_t)(bj * BN) * D;

    // per-thread load indices: 1024 16B chunks per tile, 4 per thread
    const int lrow0 = tid >> 3;        // used with +32*i
    const int lcol  = tid & 7;         // 16B chunk within 128B row

    float acc[4][4][4];
    #pragma unroll
    for (int f = 0; f < 4; ++f)
        #pragma unroll
        for (int g = 0; g < 4; ++g)
            #pragma unroll
            for (int r = 0; r < 4; ++r) acc[f][g][r] = 0.f;

    // ldmatrix per-thread row/col components
    const int a_row = warp_m * 64 + ((lane >> 3) & 1) * 8 + (lane & 7); // + f*16
    const int a_cb  = (lane >> 4) * 16;                                  // byte col, + ks*32
    const int b_row = warp_n * 32 + ((lane >> 4) & 1) * 8 + (lane & 7); // + nf2*16
    const int b_cb  = ((lane >> 3) & 1) * 16;                            // + ks*32

    // prologue: load kc=0 into buf 0
    {
        const int kt = 0;
        #pragma unroll
        for (int i = 0; i < 4; ++i) {
            int row = lrow0 + i * 32;
            cp_async16(sbase + SM_A0 + swz128(row * 128 + lcol * 16),
                       Wt + (size_t)row * D + kt + lcol * 8);
            cp_async16(sbase + SM_B0 + swz128(row * 128 + lcol * 16),
                       Ot + (size_t)row * D + kt + lcol * 8);
        }
        CP_COMMIT();
    }

    #pragma unroll 1
    for (int kc = 0; kc < NKC; ++kc) {
        const int b = kc & 1;
        CP_WAIT0();
        __syncthreads();

        if (kc + 1 < NKC) {
            const int kt = (kc + 1) * BK;
            const uint32_t sa = sbase + (b ? SM_A0 : SM_A1);
            const uint32_t sb = sbase + (b ? SM_B0 : SM_B1);
            #pragma unroll
            for (int i = 0; i < 4; ++i) {
                int row = lrow0 + i * 32;
                cp_async16(sa + swz128(row * 128 + lcol * 16),
                           Wt + (size_t)row * D + kt + lcol * 8);
                cp_async16(sb + swz128(row * 128 + lcol * 16),
                           Ot + (size_t)row * D + kt + lcol * 8);
            }
            CP_COMMIT();
        }

        const uint32_t abuf = sbase + (b ? SM_A1 : SM_A0);
        const uint32_t bbuf = sbase + (b ? SM_B1 : SM_B0);

        #pragma unroll
        for (int ks = 0; ks < 4; ++ks) {
            uint32_t areg[4][4];
            uint32_t breg[2][4];
            #pragma unroll
            for (int f = 0; f < 4; ++f)
                ldsm_x4(areg[f], abuf + swz128((a_row + f * 16) * 128 + a_cb + ks * 32));
            #pragma unroll
            for (int nf2 = 0; nf2 < 2; ++nf2)
                ldsm_x4(breg[nf2], bbuf + swz128((b_row + nf2 * 16) * 128 + b_cb + ks * 32));
            #pragma unroll
            for (int f = 0; f < 4; ++f)
                #pragma unroll
                for (int g = 0; g < 4; ++g)
                    mma_bf16(acc[f][g], areg[f], &breg[g >> 1][(g & 1) * 2]);
        }
        __syncthreads();
    }

    // ---- fused epilogue ------------------------------------------------------
    const float* snw = reinterpret_cast<const float*>(smem + SM_NW);
    const float* sd  = reinterpret_cast<const float*>(smem + SM_D);
    const float* sno = reinterpret_cast<const float*>(smem + SM_NO);

    const int qrow = lane >> 2;        // 0..7
    const int qcol = (lane & 3) * 2;   // 0,2,4,6

    float lsum = 0.f;
    #pragma unroll
    for (int f = 0; f < 4; ++f) {
        const int r0 = warp_m * 64 + f * 16 + qrow;
        #pragma unroll
        for (int half = 0; half < 2; ++half) {       // +0 / +8 row
            const int rl = r0 + half * 8;
            const int rg = bi * BM + rl;
            const float nw_r = snw[rl];
            const float d_r  = sd[rl];
            #pragma unroll
            for (int g = 0; g < 4; ++g) {
                #pragma unroll
                for (int e = 0; e < 2; ++e) {
                    const int cl = warp_n * 32 + g * 8 + qcol + e;
                    const int jg = bj * BN + cl;
                    const float S = acc[f][g][half * 2 + e] *
                                    __fdividef(1.0f, fmaxf(nw_r * sno[cl], EPSV));
                    lsum += (rg == jg) ? (1.0f - S) : fmaxf(MARGIN - S + d_r, 0.0f);
                }
            }
        }
    }

    lsum = warp_sum(lsum);
    __shared__ float red[8];
    if (lane == 0) red[wid] = lsum;
    __syncthreads();
    if (wid == 0) {
        float v = (lane < 8) ? red[lane] : 0.f;
        v = warp_sum(v);
        if (lane == 0) atomicAdd(&g_acc, (double)v);
    }
}

// ---------------- kernel 3: finalize -----------------------------------------
__global__ void finalize_kernel(float* __restrict__ out) {
    if (threadIdx.x == 0 && blockIdx.x == 0) {
        out[0] = (float)(g_acc / ((double)N * (double)N));
        g_acc = 0.0;
    }
}

extern "C" void kernel_launch(void* const* d_in, const int* in_sizes, int n_in,
                              void* d_out, int out_size) {
    const float* W = (const float*)d_in[0];
    const float* O = (const float*)d_in[1];
    float* out = (float*)d_out;

    cudaFuncSetAttribute(gemm_loss_mma, cudaFuncAttributeMaxDynamicSharedMemorySize, SM_TOTAL);

    row_stats_kernel<<<N, 256>>>(W, O);

    dim3 grid(N / BN, N / BM);   // (32, 32)
    gemm_loss_mma<<<grid, 256, SM_TOTAL>>>();

    finalize_kernel<<<1, 32>>>(out);
}